// round 11
// baseline (speedup 1.0000x reference)
#include <cuda_runtime.h>
#include <cuda_fp16.h>
#include <math.h>
#include <stdint.h>

#define MAXN 50000
#define MAXE 1600000
#define HH 256

// ---------------------------------------------------------------------------
// Scratch (no allocations allowed anywhere).
// ---------------------------------------------------------------------------
__device__ __half g_x16[(size_t)MAXN * HH];   // gathered emb, fp16
__device__ __half g_h16[(size_t)MAXN * HH];   // layer-0 output, fp16
__device__ int    g_cnt[MAXN];
__device__ int    g_rowptr[MAXN + 1];
__device__ int    g_cursor[MAXN];
__device__ int    g_csr_src[MAXE];
__device__ float  g_deginv[MAXN];
__device__ float  g_normsq;
__device__ int    g_bsum[64];
__device__ int    g_boff[64];
// Transposed fp16 weights: Wt[n][k], n=0..255, k=0..511
__device__ __half g_Wt0[256 * 512];
__device__ __half g_Wt1[256 * 512];

__device__ __forceinline__ void mma_f16(float& c0, float& c1, float& c2, float& c3,
                                        uint32_t a0, uint32_t a1, uint32_t a2, uint32_t a3,
                                        uint32_t b0, uint32_t b1) {
    asm volatile(
        "mma.sync.aligned.m16n8k16.row.col.f32.f16.f16.f32 "
        "{%0,%1,%2,%3}, {%4,%5,%6,%7}, {%8,%9}, {%0,%1,%2,%3};"
        : "+f"(c0), "+f"(c1), "+f"(c2), "+f"(c3)
        : "r"(a0), "r"(a1), "r"(a2), "r"(a3), "r"(b0), "r"(b1));
}

// ---------------------------------------------------------------------------
// CSR build: histogram -> 3-stage multi-block scan -> scatter  (R7-proven)
// ---------------------------------------------------------------------------
__global__ void hist_kernel(const int* __restrict__ edst, int E) {
    int e = blockIdx.x * blockDim.x + threadIdx.x;
    if (e < E) atomicAdd(&g_cnt[edst[e]], 1);
}

__global__ void scan_part(int N) {
    int i = blockIdx.x * 1024 + threadIdx.x;
    int v = (i < N) ? g_cnt[i] : 0;
    __shared__ int sh[32];
    int lane = threadIdx.x & 31, wid = threadIdx.x >> 5;
    int s = v;
    #pragma unroll
    for (int o = 16; o; o >>= 1) s += __shfl_down_sync(~0u, s, o);
    if (lane == 0) sh[wid] = s;
    __syncthreads();
    if (wid == 0) {
        int t = sh[lane];
        #pragma unroll
        for (int o = 16; o; o >>= 1) t += __shfl_down_sync(~0u, t, o);
        if (lane == 0) g_bsum[blockIdx.x] = t;
    }
}

__global__ void scan_top(int NB) {
    if (threadIdx.x == 0) {
        int acc = 0;
        for (int b = 0; b < NB; b++) { g_boff[b] = acc; acc += g_bsum[b]; }
    }
}

__global__ void scan_final(int N) {
    int i = blockIdx.x * 1024 + threadIdx.x;
    int v = (i < N) ? g_cnt[i] : 0;
    int lane = threadIdx.x & 31, wid = threadIdx.x >> 5;
    int inc = v;
    #pragma unroll
    for (int o = 1; o < 32; o <<= 1) {
        int t = __shfl_up_sync(~0u, inc, o);
        if (lane >= o) inc += t;
    }
    __shared__ int sh[32];
    if (lane == 31) sh[wid] = inc;
    __syncthreads();
    if (wid == 0) {
        int t = sh[lane];
        int e = t;
        #pragma unroll
        for (int o = 1; o < 32; o <<= 1) {
            int u = __shfl_up_sync(~0u, e, o);
            if (lane >= o) e += u;
        }
        sh[lane] = e - t;
    }
    __syncthreads();
    int exc = g_boff[blockIdx.x] + sh[wid] + inc - v;
    if (i < N) {
        g_rowptr[i] = exc;
        g_cursor[i] = exc;
        g_deginv[i] = 1.0f / fmaxf((float)v, 1.0f);
        if (i == N - 1) g_rowptr[N] = exc + v;
    }
}

__global__ void fill_kernel(const int* __restrict__ esrc,
                            const int* __restrict__ edst, int E) {
    int e = blockIdx.x * blockDim.x + threadIdx.x;
    if (e < E) {
        int pos = atomicAdd(&g_cursor[edst[e]], 1);
        g_csr_src[pos] = esrc[e];
    }
}

// ---------------------------------------------------------------------------
// Weight transpose to fp16: Wt16[n*512 + k] = (half)Wext[k][n]
// ---------------------------------------------------------------------------
__global__ void wtrans_kernel(const float* __restrict__ Ws,
                              const float* __restrict__ Wn,
                              __half* __restrict__ Wt) {
    int i = blockIdx.x * blockDim.x + threadIdx.x;
    if (i >= 256 * 512) return;
    int n = i >> 9;
    int k = i & 511;
    float v = (k < 256) ? Ws[(size_t)k * 256 + n]
                        : Wn[(size_t)(k - 256) * 256 + n];
    Wt[i] = __float2half_rn(v);
}

// ---------------------------------------------------------------------------
// fp16 pre-gather of emb: g_x16[row] = fp16(emb[idx[row]])
// ---------------------------------------------------------------------------
__global__ void conv16_kernel(const float* __restrict__ emb,
                              const int* __restrict__ idx, int N) {
    int t = blockIdx.x * blockDim.x + threadIdx.x;
    int row = t >> 6;
    if (row >= N) return;
    int c = (t & 63) * 4;
    int ar = __ldg(idx + row);
    float4 v = *reinterpret_cast<const float4*>(emb + (size_t)ar * 256 + c);
    __half2 h0 = __floats2half2_rn(v.x, v.y);
    __half2 h1 = __floats2half2_rn(v.z, v.w);
    uint2 packed = make_uint2(*(uint32_t*)&h0, *(uint32_t*)&h1);
    *reinterpret_cast<uint2*>(g_x16 + (size_t)row * HH + c) = packed;
}

// ---------------------------------------------------------------------------
// FUSED agg + GEMM per layer.
//   C[128-row-tile, 256] = [self16 | mean-gather(nbrs)] (K=512) @ Wt + bias
// 512 threads = 16 warps (2x8), warp tile 64x32 (R7 fragment math),
// BK=32, double-buffered SA/SB (stride 40), one sync per chunk.
// Neighbor K-chunks: A-tile filled by JIT CSR gather-mean (no g_agg buffer).
// SMEM halfs: SA0@0 SA1@5120 SB0@10240 SB1@20480  (total 61440 B)
// ---------------------------------------------------------------------------
template<bool RELU, bool SUMSQ, bool OUT16>
__global__ __launch_bounds__(512, 1)
void sage_fused(const __half* __restrict__ Self16,
                const __half* __restrict__ Wt,
                const float* __restrict__ bias,
                float* __restrict__ Cout, int N)
{
    extern __shared__ __half sm16[];
    __shared__ float s_warpss[16];

    const int tid  = threadIdx.x;
    const int wid  = tid >> 5;
    const int lane = tid & 31;
    const int g    = lane >> 2;
    const int t    = lane & 3;
    const int rowbase = blockIdx.x * 128;

    const int wm = (wid >> 3) * 64;   // 0 or 64
    const int wn = (wid & 7) * 32;    // 0..224

    // gather identity: fixed per thread for the whole kernel
    const int grow = tid >> 2;        // 0..127 (local row)
    const int gq   = tid & 3;         // 8-half column group within 32-half chunk
    const int gnode = rowbase + grow;
    int rp0 = 0, rp1 = 0;
    float dv = 0.0f;
    if (gnode < N) {
        rp0 = g_rowptr[gnode];
        rp1 = g_rowptr[gnode + 1];
        dv  = g_deginv[gnode];
    }

    float c[4][4][4];
    #pragma unroll
    for (int mt = 0; mt < 4; mt++)
        #pragma unroll
        for (int nt = 0; nt < 4; nt++)
            #pragma unroll
            for (int j = 0; j < 4; j++) c[mt][nt][j] = 0.0f;

    int aoff[4], boff[4];
    #pragma unroll
    for (int mt = 0; mt < 4; mt++) aoff[mt] = (wm + mt * 16 + g) * 40 + 2 * t;
    #pragma unroll
    for (int nt = 0; nt < 4; nt++) boff[nt] = (wn + nt * 8 + g) * 40 + 2 * t;

    auto fill = [&](int kt, int buf) {
        __half* SA = sm16 + buf * 5120;
        __half* SB = sm16 + 10240 + buf * 10240;
        const int k0 = kt * 32;

        // ---- B chunk: 256 n-rows x 32 k, 2 uint4 per thread ----
        #pragma unroll
        for (int i = 0; i < 2; i++) {
            int row = grow + i * 128;      // 0..255
            *reinterpret_cast<uint4*>(SB + row * 40 + gq * 8) =
                *reinterpret_cast<const uint4*>(Wt + (size_t)row * 512 + k0 + gq * 8);
        }

        // ---- A chunk ----
        if (k0 < 256) {
            // self half: straight copy
            uint4 v = make_uint4(0, 0, 0, 0);
            if (gnode < N)
                v = *reinterpret_cast<const uint4*>(
                    Self16 + (size_t)gnode * 256 + k0 + gq * 8);
            *reinterpret_cast<uint4*>(SA + grow * 40 + gq * 8) = v;
        } else {
            // neighbor half: JIT gather-mean over CSR, 8 cols per thread
            const int kk = (k0 - 256) + gq * 8;
            float acc[8];
            #pragma unroll
            for (int j = 0; j < 8; j++) acc[j] = 0.0f;

            int i = rp0;
            for (; i + 2 <= rp1; i += 2) {
                int s0 = __ldg(g_csr_src + i);
                int s1 = __ldg(g_csr_src + i + 1);
                uint4 r0 = *reinterpret_cast<const uint4*>(Self16 + (size_t)s0 * 256 + kk);
                uint4 r1 = *reinterpret_cast<const uint4*>(Self16 + (size_t)s1 * 256 + kk);
                const uint32_t* w0 = &r0.x;
                const uint32_t* w1 = &r1.x;
                #pragma unroll
                for (int j = 0; j < 4; j++) {
                    float2 f0 = __half22float2(*(const __half2*)&w0[j]);
                    float2 f1 = __half22float2(*(const __half2*)&w1[j]);
                    acc[j * 2 + 0] += f0.x + f1.x;
                    acc[j * 2 + 1] += f0.y + f1.y;
                }
            }
            if (i < rp1) {
                int s = __ldg(g_csr_src + i);
                uint4 r = *reinterpret_cast<const uint4*>(Self16 + (size_t)s * 256 + kk);
                const uint32_t* w = &r.x;
                #pragma unroll
                for (int j = 0; j < 4; j++) {
                    float2 f = __half22float2(*(const __half2*)&w[j]);
                    acc[j * 2 + 0] += f.x;
                    acc[j * 2 + 1] += f.y;
                }
            }

            uint4 o;
            uint32_t* ow = &o.x;
            #pragma unroll
            for (int j = 0; j < 4; j++) {
                __half2 h = __floats2half2_rn(acc[j * 2] * dv, acc[j * 2 + 1] * dv);
                ow[j] = *(uint32_t*)&h;
            }
            *reinterpret_cast<uint4*>(SA + grow * 40 + gq * 8) = o;
        }
    };

    fill(0, 0);
    __syncthreads();

    #pragma unroll 1
    for (int kt = 0; kt < 16; kt++) {
        const int buf = kt & 1;
        if (kt + 1 < 16) fill(kt + 1, buf ^ 1);

        const __half* SA = sm16 + buf * 5120;
        const __half* SB = sm16 + 10240 + buf * 10240;

        #pragma unroll
        for (int ks = 0; ks < 2; ks++) {
            const int kb = ks * 16;
            uint32_t af[4][4], bf[4][2];
            #pragma unroll
            for (int mt = 0; mt < 4; mt++) {
                af[mt][0] = *reinterpret_cast<const uint32_t*>(SA + aoff[mt] + kb);
                af[mt][1] = *reinterpret_cast<const uint32_t*>(SA + aoff[mt] + kb + 320);
                af[mt][2] = *reinterpret_cast<const uint32_t*>(SA + aoff[mt] + kb + 8);
                af[mt][3] = *reinterpret_cast<const uint32_t*>(SA + aoff[mt] + kb + 328);
            }
            #pragma unroll
            for (int nt = 0; nt < 4; nt++) {
                bf[nt][0] = *reinterpret_cast<const uint32_t*>(SB + boff[nt] + kb);
                bf[nt][1] = *reinterpret_cast<const uint32_t*>(SB + boff[nt] + kb + 8);
            }
            #pragma unroll
            for (int mt = 0; mt < 4; mt++)
                #pragma unroll
                for (int nt = 0; nt < 4; nt++)
                    mma_f16(c[mt][nt][0], c[mt][nt][1], c[mt][nt][2], c[mt][nt][3],
                            af[mt][0], af[mt][1], af[mt][2], af[mt][3],
                            bf[nt][0], bf[nt][1]);
        }
        __syncthreads();
    }

    // ---- epilogue ----
    float ss = 0.0f;
    #pragma unroll
    for (int nt = 0; nt < 4; nt++) {
        int col = wn + nt * 8 + 2 * t;
        float2 bv = *reinterpret_cast<const float2*>(bias + col);
        #pragma unroll
        for (int mt = 0; mt < 4; mt++) {
            int r0 = rowbase + wm + mt * 16 + g;
            float x0 = c[mt][nt][0] + bv.x;
            float x1 = c[mt][nt][1] + bv.y;
            float x2 = c[mt][nt][2] + bv.x;
            float x3 = c[mt][nt][3] + bv.y;
            if (RELU) { x0 = fmaxf(x0, 0.f); x1 = fmaxf(x1, 0.f);
                        x2 = fmaxf(x2, 0.f); x3 = fmaxf(x3, 0.f); }
            if (r0 < N) {
                if (OUT16) {
                    __half2 h = __floats2half2_rn(x0, x1);
                    *reinterpret_cast<__half2*>(g_h16 + (size_t)r0 * 256 + col) = h;
                } else {
                    *reinterpret_cast<float2*>(Cout + (size_t)r0 * 256 + col) =
                        make_float2(x0, x1);
                }
                if (SUMSQ) { ss = fmaf(x0, x0, ss); ss = fmaf(x1, x1, ss); }
            }
            if (r0 + 8 < N) {
                if (OUT16) {
                    __half2 h = __floats2half2_rn(x2, x3);
                    *reinterpret_cast<__half2*>(g_h16 + (size_t)(r0 + 8) * 256 + col) = h;
                } else {
                    *reinterpret_cast<float2*>(Cout + (size_t)(r0 + 8) * 256 + col) =
                        make_float2(x2, x3);
                }
                if (SUMSQ) { ss = fmaf(x2, x2, ss); ss = fmaf(x3, x3, ss); }
            }
        }
    }

    if (SUMSQ) {
        #pragma unroll
        for (int off = 16; off; off >>= 1)
            ss += __shfl_down_sync(0xffffffffu, ss, off);
        if (lane == 0) s_warpss[wid] = ss;
        __syncthreads();
        if (tid == 0) {
            float tot = 0.0f;
            #pragma unroll
            for (int w = 0; w < 16; w++) tot += s_warpss[w];
            atomicAdd(&g_normsq, tot);
        }
    }
}

// ---------------------------------------------------------------------------
__global__ void scale_kernel(float* __restrict__ out, long long total4) {
    float s = rsqrtf(g_normsq);
    long long stride = (long long)gridDim.x * blockDim.x;
    for (long long i = (long long)blockIdx.x * blockDim.x + threadIdx.x;
         i < total4; i += stride) {
        float4 v = reinterpret_cast<float4*>(out)[i];
        v.x *= s; v.y *= s; v.z *= s; v.w *= s;
        reinterpret_cast<float4*>(out)[i] = v;
    }
}

// ---------------------------------------------------------------------------
extern "C" void kernel_launch(void* const* d_in, const int* in_sizes, int n_in,
                              void* d_out, int out_size) {
    const int*   input_nodes = (const int*)  d_in[0];
    const int*   esrc        = (const int*)  d_in[1];
    const int*   edst        = (const int*)  d_in[2];
    const float* emb         = (const float*)d_in[3];
    const float* Ws0         = (const float*)d_in[4];
    const float* Wn0         = (const float*)d_in[5];
    const float* b0          = (const float*)d_in[6];
    const float* Ws1         = (const float*)d_in[7];
    const float* Wn1         = (const float*)d_in[8];
    const float* b1          = (const float*)d_in[9];

    int N = in_sizes[0];
    int E = in_sizes[1];
    float* out = (float*)d_out;

    void *p_cnt, *p_norm, *p_w0, *p_w1, *p_x16, *p_h16;
    cudaGetSymbolAddress(&p_cnt,  g_cnt);
    cudaGetSymbolAddress(&p_norm, g_normsq);
    cudaGetSymbolAddress(&p_w0,   g_Wt0);
    cudaGetSymbolAddress(&p_w1,   g_Wt1);
    cudaGetSymbolAddress(&p_x16,  g_x16);
    cudaGetSymbolAddress(&p_h16,  g_h16);
    const __half* Wt0 = (const __half*)p_w0;
    const __half* Wt1 = (const __half*)p_w1;
    const __half* x16 = (const __half*)p_x16;
    const __half* h16 = (const __half*)p_h16;

    const size_t SMEM_FUSED = 30720 * sizeof(__half);  // 61440 B
    cudaFuncSetAttribute(sage_fused<true, false, true>,
                         cudaFuncAttributeMaxDynamicSharedMemorySize, (int)SMEM_FUSED);
    cudaFuncSetAttribute(sage_fused<false, true, false>,
                         cudaFuncAttributeMaxDynamicSharedMemorySize, (int)SMEM_FUSED);

    cudaMemsetAsync(p_cnt,  0, (size_t)N * sizeof(int), 0);
    cudaMemsetAsync(p_norm, 0, sizeof(float), 0);

    // independent prep
    wtrans_kernel<<<512, 256>>>(Ws0, Wn0, (__half*)p_w0);
    wtrans_kernel<<<512, 256>>>(Ws1, Wn1, (__half*)p_w1);
    conv16_kernel<<<(N * 64 + 255) / 256, 256>>>(emb, input_nodes, N);

    // CSR build
    int NB = (N + 1023) / 1024;
    hist_kernel<<<(E + 255) / 256, 256>>>(edst, E);
    scan_part<<<NB, 1024>>>(N);
    scan_top<<<1, 32>>>(NB);
    scan_final<<<NB, 1024>>>(N);
    fill_kernel<<<(E + 255) / 256, 256>>>(esrc, edst, E);

    int gemmB = (N + 127) / 128;   // 391

    // layer 0: fused agg+GEMM -> h16
    sage_fused<true, false, true><<<gemmB, 512, SMEM_FUSED>>>(
        x16, Wt0, b0, nullptr, N);

    // layer 1: fused agg+GEMM -> out (fp32) + sumsq
    sage_fused<false, true, false><<<gemmB, 512, SMEM_FUSED>>>(
        h16, Wt1, b1, out, N);

    long long total4 = ((long long)N * HH) / 4;
    scale_kernel<<<2048, 256>>>(out, total4);
}

// round 12
// speedup vs baseline: 1.3589x; 1.3589x over previous
#include <cuda_runtime.h>
#include <cuda_fp16.h>
#include <math.h>
#include <stdint.h>

#define MAXN 50000
#define MAXE 1600000
#define HH 256

// ---------------------------------------------------------------------------
// Scratch (no allocations allowed anywhere).
// ---------------------------------------------------------------------------
__device__ __half g_agg16[(size_t)MAXN * HH]; // mean-aggregated neighbor feats (fp16)
__device__ __half g_x16[(size_t)MAXN * HH];   // gathered emb, fp16
__device__ __half g_h16[(size_t)MAXN * HH];   // layer-0 output, fp16
__device__ int    g_cnt[MAXN];
__device__ int    g_rowptr[MAXN + 1];
__device__ int    g_cursor[MAXN];
__device__ int    g_csr_src[MAXE];
__device__ float  g_deginv[MAXN];
__device__ float  g_normsq;
__device__ int    g_bsum[64];
__device__ int    g_boff[64];
// Transposed fp16 weights: Wt[n][k], n=0..255, k=0..511
__device__ __half g_Wt0[256 * 512];
__device__ __half g_Wt1[256 * 512];

__device__ __forceinline__ void mma_f16(float& c0, float& c1, float& c2, float& c3,
                                        uint32_t a0, uint32_t a1, uint32_t a2, uint32_t a3,
                                        uint32_t b0, uint32_t b1) {
    asm volatile(
        "mma.sync.aligned.m16n8k16.row.col.f32.f16.f16.f32 "
        "{%0,%1,%2,%3}, {%4,%5,%6,%7}, {%8,%9}, {%0,%1,%2,%3};"
        : "+f"(c0), "+f"(c1), "+f"(c2), "+f"(c3)
        : "r"(a0), "r"(a1), "r"(a2), "r"(a3), "r"(b0), "r"(b1));
}

// ---------------------------------------------------------------------------
// CSR build: histogram -> 3-stage multi-block scan -> scatter
// ---------------------------------------------------------------------------
__global__ void hist_kernel(const int* __restrict__ edst, int E) {
    int e = blockIdx.x * blockDim.x + threadIdx.x;
    if (e < E) atomicAdd(&g_cnt[edst[e]], 1);
}

__global__ void scan_part(int N) {
    int i = blockIdx.x * 1024 + threadIdx.x;
    int v = (i < N) ? g_cnt[i] : 0;
    __shared__ int sh[32];
    int lane = threadIdx.x & 31, wid = threadIdx.x >> 5;
    int s = v;
    #pragma unroll
    for (int o = 16; o; o >>= 1) s += __shfl_down_sync(~0u, s, o);
    if (lane == 0) sh[wid] = s;
    __syncthreads();
    if (wid == 0) {
        int t = sh[lane];
        #pragma unroll
        for (int o = 16; o; o >>= 1) t += __shfl_down_sync(~0u, t, o);
        if (lane == 0) g_bsum[blockIdx.x] = t;
    }
}

__global__ void scan_top(int NB) {
    if (threadIdx.x == 0) {
        int acc = 0;
        for (int b = 0; b < NB; b++) { g_boff[b] = acc; acc += g_bsum[b]; }
    }
}

__global__ void scan_final(int N) {
    int i = blockIdx.x * 1024 + threadIdx.x;
    int v = (i < N) ? g_cnt[i] : 0;
    int lane = threadIdx.x & 31, wid = threadIdx.x >> 5;
    int inc = v;
    #pragma unroll
    for (int o = 1; o < 32; o <<= 1) {
        int t = __shfl_up_sync(~0u, inc, o);
        if (lane >= o) inc += t;
    }
    __shared__ int sh[32];
    if (lane == 31) sh[wid] = inc;
    __syncthreads();
    if (wid == 0) {
        int t = sh[lane];
        int e = t;
        #pragma unroll
        for (int o = 1; o < 32; o <<= 1) {
            int u = __shfl_up_sync(~0u, e, o);
            if (lane >= o) e += u;
        }
        sh[lane] = e - t;
    }
    __syncthreads();
    int exc = g_boff[blockIdx.x] + sh[wid] + inc - v;
    if (i < N) {
        g_rowptr[i] = exc;
        g_cursor[i] = exc;
        g_deginv[i] = 1.0f / fmaxf((float)v, 1.0f);
        if (i == N - 1) g_rowptr[N] = exc + v;
    }
}

__global__ void fill_kernel(const int* __restrict__ esrc,
                            const int* __restrict__ edst, int E) {
    int e = blockIdx.x * blockDim.x + threadIdx.x;
    if (e < E) {
        int pos = atomicAdd(&g_cursor[edst[e]], 1);
        g_csr_src[pos] = esrc[e];
    }
}

// ---------------------------------------------------------------------------
// Weight transpose to fp16: Wt16[n*512 + k] = (half)Wext[k][n]
// ---------------------------------------------------------------------------
__global__ void wtrans_kernel(const float* __restrict__ Ws,
                              const float* __restrict__ Wn,
                              __half* __restrict__ Wt) {
    int i = blockIdx.x * blockDim.x + threadIdx.x;
    if (i >= 256 * 512) return;
    int n = i >> 9;
    int k = i & 511;
    float v = (k < 256) ? Ws[(size_t)k * 256 + n]
                        : Wn[(size_t)(k - 256) * 256 + n];
    Wt[i] = __float2half_rn(v);
}

// ---------------------------------------------------------------------------
// fp16 pre-gather of emb: g_x16[row] = fp16(emb[idx[row]])
// ---------------------------------------------------------------------------
__global__ void conv16_kernel(const float* __restrict__ emb,
                              const int* __restrict__ idx, int N) {
    int t = blockIdx.x * blockDim.x + threadIdx.x;
    int row = t >> 6;
    if (row >= N) return;
    int c = (t & 63) * 4;
    int ar = __ldg(idx + row);
    float4 v = *reinterpret_cast<const float4*>(emb + (size_t)ar * 256 + c);
    __half2 h0 = __floats2half2_rn(v.x, v.y);
    __half2 h1 = __floats2half2_rn(v.z, v.w);
    uint2 packed = make_uint2(*(uint32_t*)&h0, *(uint32_t*)&h1);
    *reinterpret_cast<uint2*>(g_x16 + (size_t)row * HH + c) = packed;
}

// ---------------------------------------------------------------------------
// fp16 gather-based mean aggregation (R7 layout: 64 thr/node, uint2 lanes)
// ---------------------------------------------------------------------------
__global__ __launch_bounds__(256, 8)
void agg_gather16(const __half* __restrict__ feat16, int N)
{
    int node = blockIdx.x * 4 + (threadIdx.x >> 6);
    if (node >= N) return;
    int c = (threadIdx.x & 63) * 4;

    int b = g_rowptr[node];
    int e = g_rowptr[node + 1];

    float4 acc = make_float4(0.f, 0.f, 0.f, 0.f);
    int i = b;
    for (; i + 4 <= e; i += 4) {
        int s0 = g_csr_src[i + 0];
        int s1 = g_csr_src[i + 1];
        int s2 = g_csr_src[i + 2];
        int s3 = g_csr_src[i + 3];
        uint2 r0 = *reinterpret_cast<const uint2*>(feat16 + (size_t)s0 * HH + c);
        uint2 r1 = *reinterpret_cast<const uint2*>(feat16 + (size_t)s1 * HH + c);
        uint2 r2 = *reinterpret_cast<const uint2*>(feat16 + (size_t)s2 * HH + c);
        uint2 r3 = *reinterpret_cast<const uint2*>(feat16 + (size_t)s3 * HH + c);
        float2 a0 = __half22float2(*(__half2*)&r0.x), b0f = __half22float2(*(__half2*)&r0.y);
        float2 a1 = __half22float2(*(__half2*)&r1.x), b1f = __half22float2(*(__half2*)&r1.y);
        float2 a2 = __half22float2(*(__half2*)&r2.x), b2f = __half22float2(*(__half2*)&r2.y);
        float2 a3 = __half22float2(*(__half2*)&r3.x), b3f = __half22float2(*(__half2*)&r3.y);
        acc.x += (a0.x + a1.x) + (a2.x + a3.x);
        acc.y += (a0.y + a1.y) + (a2.y + a3.y);
        acc.z += (b0f.x + b1f.x) + (b2f.x + b3f.x);
        acc.w += (b0f.y + b1f.y) + (b2f.y + b3f.y);
    }
    for (; i < e; i++) {
        int s = g_csr_src[i];
        uint2 r = *reinterpret_cast<const uint2*>(feat16 + (size_t)s * HH + c);
        float2 a = __half22float2(*(__half2*)&r.x);
        float2 bb = __half22float2(*(__half2*)&r.y);
        acc.x += a.x; acc.y += a.y; acc.z += bb.x; acc.w += bb.y;
    }

    float dv = g_deginv[node];
    __half2 h0 = __floats2half2_rn(acc.x * dv, acc.y * dv);
    __half2 h1 = __floats2half2_rn(acc.z * dv, acc.w * dv);
    uint2 packed = make_uint2(*(uint32_t*)&h0, *(uint32_t*)&h1);
    *reinterpret_cast<uint2*>(g_agg16 + (size_t)node * HH + c) = packed;
}

// ---------------------------------------------------------------------------
// fp16 mma.sync fused SAGE GEMM (exact R7 core, warp-level sumsq)
// ---------------------------------------------------------------------------
template<bool RELU, bool SUMSQ, bool OUT16>
__global__ __launch_bounds__(256)
void sage_gemm_mma16(const __half* __restrict__ Self16,
                     const __half* __restrict__ Wt,
                     const float* __restrict__ bias,
                     float* __restrict__ Cout, int N)
{
    extern __shared__ __half sm16[];

    const int tid  = threadIdx.x;
    const int wid  = tid >> 5;
    const int lane = tid & 31;
    const int g    = lane >> 2;
    const int t    = lane & 3;
    const int rowbase = blockIdx.y * 128;
    const int colbase = blockIdx.x * 128;

    const int wm = (wid >> 2) * 64;
    const int wn = (wid & 3) * 32;

    const int lr = tid >> 1;
    const int lq = tid & 1;

    float c[4][4][4];
    #pragma unroll
    for (int mt = 0; mt < 4; mt++)
        #pragma unroll
        for (int nt = 0; nt < 4; nt++)
            #pragma unroll
            for (int j = 0; j < 4; j++) c[mt][nt][j] = 0.0f;

    int aoff[4], boff[4];
    #pragma unroll
    for (int mt = 0; mt < 4; mt++) aoff[mt] = (wm + mt * 16 + g) * 40 + 2 * t;
    #pragma unroll
    for (int nt = 0; nt < 4; nt++) boff[nt] = (wn + nt * 8 + g) * 40 + 2 * t;

    uint4 aR[2], bR[2];

    auto load_tile = [&](int kt) {
        const int k0 = kt * 32;
        const bool neigh = (k0 >= 256);
        const __half* src = neigh ? (const __half*)g_agg16 : Self16;
        const int kk = neigh ? (k0 - 256) : k0;
        int row = rowbase + lr;
        #pragma unroll
        for (int i = 0; i < 2; i++) {
            int q = lq + i * 2;
            uint4 v = make_uint4(0, 0, 0, 0);
            if (row < N)
                v = *reinterpret_cast<const uint4*>(src + (size_t)row * 256 + kk + q * 8);
            aR[i] = v;
        }
        #pragma unroll
        for (int i = 0; i < 2; i++) {
            int q = lq + i * 2;
            bR[i] = *reinterpret_cast<const uint4*>(
                Wt + (size_t)(colbase + lr) * 512 + k0 + q * 8);
        }
    };

    auto store_tile = [&](int buf) {
        __half* SA = sm16 + buf * 5120;
        __half* SB = sm16 + 10240 + buf * 5120;
        #pragma unroll
        for (int i = 0; i < 2; i++) {
            int q = lq + i * 2;
            *reinterpret_cast<uint4*>(SA + lr * 40 + q * 8) = aR[i];
        }
        #pragma unroll
        for (int i = 0; i < 2; i++) {
            int q = lq + i * 2;
            *reinterpret_cast<uint4*>(SB + lr * 40 + q * 8) = bR[i];
        }
    };

    load_tile(0);
    store_tile(0);
    __syncthreads();

    #pragma unroll 1
    for (int kt = 0; kt < 16; kt++) {
        const int buf = kt & 1;
        if (kt + 1 < 16) load_tile(kt + 1);

        const __half* SA = sm16 + buf * 5120;
        const __half* SB = sm16 + 10240 + buf * 5120;

        #pragma unroll
        for (int ks = 0; ks < 2; ks++) {
            const int kb = ks * 16;
            uint32_t af[4][4], bf[4][2];
            #pragma unroll
            for (int mt = 0; mt < 4; mt++) {
                af[mt][0] = *reinterpret_cast<const uint32_t*>(SA + aoff[mt] + kb);
                af[mt][1] = *reinterpret_cast<const uint32_t*>(SA + aoff[mt] + kb + 320);
                af[mt][2] = *reinterpret_cast<const uint32_t*>(SA + aoff[mt] + kb + 8);
                af[mt][3] = *reinterpret_cast<const uint32_t*>(SA + aoff[mt] + kb + 328);
            }
            #pragma unroll
            for (int nt = 0; nt < 4; nt++) {
                bf[nt][0] = *reinterpret_cast<const uint32_t*>(SB + boff[nt] + kb);
                bf[nt][1] = *reinterpret_cast<const uint32_t*>(SB + boff[nt] + kb + 8);
            }
            #pragma unroll
            for (int mt = 0; mt < 4; mt++)
                #pragma unroll
                for (int nt = 0; nt < 4; nt++)
                    mma_f16(c[mt][nt][0], c[mt][nt][1], c[mt][nt][2], c[mt][nt][3],
                            af[mt][0], af[mt][1], af[mt][2], af[mt][3],
                            bf[nt][0], bf[nt][1]);
        }

        if (kt + 1 < 16) {
            store_tile((kt + 1) & 1);
            __syncthreads();
        }
    }

    // ---- epilogue ----
    float ss = 0.0f;
    #pragma unroll
    for (int nt = 0; nt < 4; nt++) {
        int col = colbase + wn + nt * 8 + 2 * t;
        float2 bv = *reinterpret_cast<const float2*>(bias + col);
        #pragma unroll
        for (int mt = 0; mt < 4; mt++) {
            int r0 = rowbase + wm + mt * 16 + g;
            float x0 = c[mt][nt][0] + bv.x;
            float x1 = c[mt][nt][1] + bv.y;
            float x2 = c[mt][nt][2] + bv.x;
            float x3 = c[mt][nt][3] + bv.y;
            if (RELU) { x0 = fmaxf(x0, 0.f); x1 = fmaxf(x1, 0.f);
                        x2 = fmaxf(x2, 0.f); x3 = fmaxf(x3, 0.f); }
            if (r0 < N) {
                if (OUT16) {
                    __half2 h = __floats2half2_rn(x0, x1);
                    *reinterpret_cast<__half2*>(g_h16 + (size_t)r0 * 256 + col) = h;
                } else {
                    *reinterpret_cast<float2*>(Cout + (size_t)r0 * 256 + col) =
                        make_float2(x0, x1);
                }
                if (SUMSQ) { ss = fmaf(x0, x0, ss); ss = fmaf(x1, x1, ss); }
            }
            if (r0 + 8 < N) {
                if (OUT16) {
                    __half2 h = __floats2half2_rn(x2, x3);
                    *reinterpret_cast<__half2*>(g_h16 + (size_t)(r0 + 8) * 256 + col) = h;
                } else {
                    *reinterpret_cast<float2*>(Cout + (size_t)(r0 + 8) * 256 + col) =
                        make_float2(x2, x3);
                }
                if (SUMSQ) { ss = fmaf(x2, x2, ss); ss = fmaf(x3, x3, ss); }
            }
        }
    }

    if (SUMSQ) {
        #pragma unroll
        for (int off = 16; off; off >>= 1)
            ss += __shfl_down_sync(0xffffffffu, ss, off);
        if (lane == 0) atomicAdd(&g_normsq, ss);
    }
}

// ---------------------------------------------------------------------------
__global__ void scale_kernel(float* __restrict__ out, long long total4) {
    float s = rsqrtf(g_normsq);
    long long stride = (long long)gridDim.x * blockDim.x;
    for (long long i = (long long)blockIdx.x * blockDim.x + threadIdx.x;
         i < total4; i += stride) {
        float4 v = reinterpret_cast<float4*>(out)[i];
        v.x *= s; v.y *= s; v.z *= s; v.w *= s;
        reinterpret_cast<float4*>(out)[i] = v;
    }
}

// ---------------------------------------------------------------------------
extern "C" void kernel_launch(void* const* d_in, const int* in_sizes, int n_in,
                              void* d_out, int out_size) {
    const int*   input_nodes = (const int*)  d_in[0];
    const int*   esrc        = (const int*)  d_in[1];
    const int*   edst        = (const int*)  d_in[2];
    const float* emb         = (const float*)d_in[3];
    const float* Ws0         = (const float*)d_in[4];
    const float* Wn0         = (const float*)d_in[5];
    const float* b0          = (const float*)d_in[6];
    const float* Ws1         = (const float*)d_in[7];
    const float* Wn1         = (const float*)d_in[8];
    const float* b1          = (const float*)d_in[9];

    int N = in_sizes[0];
    int E = in_sizes[1];
    float* out = (float*)d_out;

    void *p_cnt, *p_norm, *p_w0, *p_w1, *p_x16, *p_h16;
    cudaGetSymbolAddress(&p_cnt,  g_cnt);
    cudaGetSymbolAddress(&p_norm, g_normsq);
    cudaGetSymbolAddress(&p_w0,   g_Wt0);
    cudaGetSymbolAddress(&p_w1,   g_Wt1);
    cudaGetSymbolAddress(&p_x16,  g_x16);
    cudaGetSymbolAddress(&p_h16,  g_h16);
    const __half* Wt0 = (const __half*)p_w0;
    const __half* Wt1 = (const __half*)p_w1;
    const __half* x16 = (const __half*)p_x16;
    const __half* h16 = (const __half*)p_h16;

    const size_t SMEM_GEMM = 20480 * sizeof(__half);  // 40960 B
    cudaFuncSetAttribute(sage_gemm_mma16<true, false, true>,
                         cudaFuncAttributeMaxDynamicSharedMemorySize, (int)SMEM_GEMM);
    cudaFuncSetAttribute(sage_gemm_mma16<false, true, false>,
                         cudaFuncAttributeMaxDynamicSharedMemorySize, (int)SMEM_GEMM);

    // Fork a side stream for the CSR-independent prep branch.
    cudaStream_t s2;
    cudaStreamCreateWithFlags(&s2, cudaStreamNonBlocking);
    cudaEvent_t evFork, evJoin;
    cudaEventCreateWithFlags(&evFork, cudaEventDisableTiming);
    cudaEventCreateWithFlags(&evJoin, cudaEventDisableTiming);

    // main stream (0): CSR chain
    cudaMemsetAsync(p_cnt,  0, (size_t)N * sizeof(int), 0);
    cudaMemsetAsync(p_norm, 0, sizeof(float), 0);
    cudaEventRecord(evFork, 0);
    cudaStreamWaitEvent(s2, evFork, 0);

    // side stream: weights + emb conversion (independent of CSR)
    wtrans_kernel<<<512, 256, 0, s2>>>(Ws0, Wn0, (__half*)p_w0);
    wtrans_kernel<<<512, 256, 0, s2>>>(Ws1, Wn1, (__half*)p_w1);
    conv16_kernel<<<(N * 64 + 255) / 256, 256, 0, s2>>>(emb, input_nodes, N);
    cudaEventRecord(evJoin, s2);

    // main stream: CSR build
    int NB = (N + 1023) / 1024;
    hist_kernel<<<(E + 255) / 256, 256>>>(edst, E);
    scan_part<<<NB, 1024>>>(N);
    scan_top<<<1, 32>>>(NB);
    scan_final<<<NB, 1024>>>(N);
    fill_kernel<<<(E + 255) / 256, 256>>>(esrc, edst, E);

    // join branches before layer 0
    cudaStreamWaitEvent(0, evJoin, 0);

    int aggB = (N + 3) / 4;
    dim3 ggrid(2, (N + 127) / 128);

    // layer 0: agg(emb16) -> GEMM -> h16
    agg_gather16<<<aggB, 256>>>(x16, N);
    sage_gemm_mma16<true, false, true><<<ggrid, 256, SMEM_GEMM>>>(
        x16, Wt0, b0, nullptr, N);

    // layer 1: agg(h16) -> GEMM -> out (fp32) + sumsq
    agg_gather16<<<aggB, 256>>>(h16, N);
    sage_gemm_mma16<false, true, false><<<ggrid, 256, SMEM_GEMM>>>(
        h16, Wt1, b1, out, N);

    long long total4 = ((long long)N * HH) / 4;
    scale_kernel<<<2048, 256>>>(out, total4);
}